// round 1
// baseline (speedup 1.0000x reference)
#include <cuda_runtime.h>
#include <cstdint>

// ---------------------------------------------------------------------------
// SwinBlock: B=32, H=W=56, C=192, heads=6, head_dim=32, WS=7, SS=3, N=49
// MLP hidden = 768. All fp32.
// ---------------------------------------------------------------------------

#define Bsz     32
#define HW      56
#define Cdim    192
#define NHEADS  6
#define HDIM    32
#define WSZ     7
#define SSH     3
#define NTOK    49              // tokens per window
#define NWIN_IMG 64             // 8x8 windows per image
#define NWIN    (Bsz * NWIN_IMG)        // 2048
#define MROWS   (NWIN * NTOK)           // 100352 == B*H*W
#define HID     768
#define SCALE   0.17677669529663687f    // 32^-0.5

// -------------------------- scratch (device globals) -----------------------
__device__ __align__(16) float g_win  [(size_t)MROWS * Cdim];   //  77 MB
__device__ __align__(16) float g_qkv  [(size_t)MROWS * 3 * Cdim]; // 231 MB
__device__ __align__(16) float g_attno[(size_t)MROWS * Cdim];   //  77 MB
__device__ __align__(16) float g_h    [(size_t)MROWS * Cdim];   //  77 MB
__device__ __align__(16) float g_ln2  [(size_t)MROWS * Cdim];   //  77 MB
__device__ __align__(16) float g_hid  [(size_t)MROWS * HID];    // 308 MB

// window-row <-> image-row permutation (same both directions):
// rw = win*49+n, win = b*64 + wh*8 + ww, n = i*7+j
// image pos = ((wh*7+i+3)%56, (ww*7+j+3)%56)
__device__ __forceinline__ int permrow(int rw) {
    int win = rw / NTOK, n = rw - win * NTOK;
    int b   = win >> 6, wi = win & 63;
    int wh  = wi >> 3,  ww = wi & 7;
    int i   = n / WSZ,  j  = n - i * WSZ;
    int hs  = wh * WSZ + i + SSH; if (hs >= HW) hs -= HW;
    int ws  = ww * WSZ + j + SSH; if (ws >= HW) ws -= HW;
    return b * (HW * HW) + hs * HW + ws;
}

// ------------------------------ LayerNorm ----------------------------------
// mode 0: LN1, read x at permuted row, write g_win at window row
// mode 1: LN2, identity rows, in -> out
__global__ void ln_kernel(const float* __restrict__ in,
                          const float* __restrict__ gamma,
                          const float* __restrict__ beta,
                          float* __restrict__ out, int remap) {
    int rw = blockIdx.x;
    int c  = threadIdx.x;                  // 0..191
    int src = remap ? permrow(rw) : rw;
    float v = in[(size_t)src * Cdim + c];

    __shared__ float red[6];
    float s = v;
    #pragma unroll
    for (int o = 16; o; o >>= 1) s += __shfl_xor_sync(0xffffffffu, s, o);
    if ((c & 31) == 0) red[c >> 5] = s;
    __syncthreads();
    float mu = 0.f;
    #pragma unroll
    for (int w = 0; w < 6; w++) mu += red[w];
    mu *= (1.0f / Cdim);
    __syncthreads();

    float d = v - mu;
    float sq = d * d;
    #pragma unroll
    for (int o = 16; o; o >>= 1) sq += __shfl_xor_sync(0xffffffffu, sq, o);
    if ((c & 31) == 0) red[c >> 5] = sq;
    __syncthreads();
    float var = 0.f;
    #pragma unroll
    for (int w = 0; w < 6; w++) var += red[w];
    var *= (1.0f / Cdim);

    out[(size_t)rw * Cdim + c] = d * rsqrtf(var + 1e-5f) * gamma[c] + beta[c];
}

// ------------------------------- SGEMM -------------------------------------
// C[M,N] = A[M,K] @ B[K,N] + bias, with epilogue:
//   0: plain   1: GELU   2: row-permute + x residual (proj)   3: +resid (out)
template<int EPI>
__global__ __launch_bounds__(256)
void sgemm_kernel(const float* __restrict__ A, const float* __restrict__ Bm,
                  const float* __restrict__ bias, float* __restrict__ C,
                  int M, int N, int K, const float* __restrict__ resid) {
    __shared__ float As[16][64];
    __shared__ float Bs[16][64];

    int tid = threadIdx.x;
    int tx = tid & 15, ty = tid >> 4;
    int mBase = blockIdx.y * 64, nBase = blockIdx.x * 64;

    float acc[4][4] = {};

    int aRow  = tid >> 2;            // 0..63
    int aCol4 = (tid & 3) * 4;       // 0..12
    int bRow  = tid >> 4;            // 0..15
    int bCol4 = (tid & 15) * 4;      // 0..60

    const float* Aptr = A + (size_t)(mBase + aRow) * K + aCol4;
    const float* Bptr = Bm + (size_t)bRow * N + nBase + bCol4;

    for (int k0 = 0; k0 < K; k0 += 16) {
        float4 av = *(const float4*)(Aptr + k0);
        As[aCol4 + 0][aRow] = av.x;
        As[aCol4 + 1][aRow] = av.y;
        As[aCol4 + 2][aRow] = av.z;
        As[aCol4 + 3][aRow] = av.w;
        float4 bv = *(const float4*)(Bptr + (size_t)k0 * N);
        *(float4*)&Bs[bRow][bCol4] = bv;
        __syncthreads();

        #pragma unroll
        for (int kk = 0; kk < 16; kk++) {
            float a0 = As[kk][ty * 4 + 0];
            float a1 = As[kk][ty * 4 + 1];
            float a2 = As[kk][ty * 4 + 2];
            float a3 = As[kk][ty * 4 + 3];
            float b0 = Bs[kk][tx * 4 + 0];
            float b1 = Bs[kk][tx * 4 + 1];
            float b2 = Bs[kk][tx * 4 + 2];
            float b3 = Bs[kk][tx * 4 + 3];
            acc[0][0] += a0 * b0; acc[0][1] += a0 * b1; acc[0][2] += a0 * b2; acc[0][3] += a0 * b3;
            acc[1][0] += a1 * b0; acc[1][1] += a1 * b1; acc[1][2] += a1 * b2; acc[1][3] += a1 * b3;
            acc[2][0] += a2 * b0; acc[2][1] += a2 * b1; acc[2][2] += a2 * b2; acc[2][3] += a2 * b3;
            acc[3][0] += a3 * b0; acc[3][1] += a3 * b1; acc[3][2] += a3 * b2; acc[3][3] += a3 * b3;
        }
        __syncthreads();
    }

    #pragma unroll
    for (int i = 0; i < 4; i++) {
        int row = mBase + ty * 4 + i;
        int prow = row;
        if (EPI == 2) prow = permrow(row);
        #pragma unroll
        for (int j = 0; j < 4; j++) {
            int col = nBase + tx * 4 + j;
            float v = acc[i][j] + bias[col];
            if (EPI == 1) {
                v = 0.5f * v * (1.0f + erff(v * 0.70710678118654752f));
            } else if (EPI == 2) {
                v += resid[(size_t)prow * Cdim + col];
            } else if (EPI == 3) {
                v += resid[(size_t)row * N + col];
            }
            C[(size_t)prow * N + col] = v;
        }
    }
}

// ----------------------------- Attention -----------------------------------
// one block per (window, head); qkv row layout: [win*49+n][t*192 + head*32 + d]
__global__ __launch_bounds__(256)
void attn_kernel(const float* __restrict__ rpb_table) {
    __shared__ float qs[NTOK][HDIM];
    __shared__ float ks[NTOK][HDIM];
    __shared__ float vs[NTOK][HDIM];
    __shared__ float S[NTOK][NTOK];

    int win  = blockIdx.x / NHEADS;
    int head = blockIdx.x - win * NHEADS;
    int tid  = threadIdx.x;

    int wi = win & 63;
    int wh = wi >> 3, ww = wi & 7;

    const float* base = g_qkv + (size_t)win * NTOK * (3 * Cdim) + head * HDIM;

    for (int idx = tid; idx < NTOK * HDIM; idx += 256) {
        int n = idx >> 5, d = idx & 31;
        const float* r = base + (size_t)n * (3 * Cdim);
        qs[n][d] = r[d] * SCALE;
        ks[n][d] = r[Cdim + d];
        vs[n][d] = r[2 * Cdim + d];
    }
    __syncthreads();

    // S[i][j] = q_i . k_j + rpb + mask
    for (int e = tid; e < NTOK * NTOK; e += 256) {
        int i = e / NTOK, j = e - i * NTOK;
        float dot = 0.f;
        #pragma unroll
        for (int d = 0; d < HDIM; d++) dot += qs[i][d] * ks[j][d];

        int ri = i / WSZ, ci = i - ri * WSZ;
        int rj = j / WSZ, cj = j - rj * WSZ;
        int rpi = (ri - rj + 6) * 13 + (ci - cj + 6);
        dot += rpb_table[rpi * NHEADS + head];

        // shift-mask: region groups on the rolled image
        int hi = wh * WSZ + ri, wiC = ww * WSZ + ci;
        int hj = wh * WSZ + rj, wjC = ww * WSZ + cj;
        int gi = (hi < 49 ? 0 : (hi < 53 ? 1 : 2)) * 3 + (wiC < 49 ? 0 : (wiC < 53 ? 1 : 2));
        int gj = (hj < 49 ? 0 : (hj < 53 ? 1 : 2)) * 3 + (wjC < 49 ? 0 : (wjC < 53 ? 1 : 2));
        if (gi != gj) dot -= 100.0f;

        S[i][j] = dot;
    }
    __syncthreads();

    // softmax per row, warp-per-row
    int warp = tid >> 5, lane = tid & 31;
    for (int r = warp; r < NTOK; r += 8) {
        float v0 = (lane < NTOK) ? S[r][lane] : -1e30f;
        float v1 = (lane + 32 < NTOK) ? S[r][lane + 32] : -1e30f;
        float m = fmaxf(v0, v1);
        #pragma unroll
        for (int o = 16; o; o >>= 1) m = fmaxf(m, __shfl_xor_sync(0xffffffffu, m, o));
        float e0 = (lane < NTOK) ? __expf(v0 - m) : 0.f;
        float e1 = (lane + 32 < NTOK) ? __expf(v1 - m) : 0.f;
        float s = e0 + e1;
        #pragma unroll
        for (int o = 16; o; o >>= 1) s += __shfl_xor_sync(0xffffffffu, s, o);
        float inv = __fdividef(1.0f, s);
        if (lane < NTOK)      S[r][lane]      = e0 * inv;
        if (lane + 32 < NTOK) S[r][lane + 32] = e1 * inv;
    }
    __syncthreads();

    // O = P @ V  -> g_attno[(win*49+n)*192 + head*32 + d]
    for (int e = tid; e < NTOK * HDIM; e += 256) {
        int n = e >> 5, d = e & 31;
        float o = 0.f;
        #pragma unroll
        for (int m = 0; m < NTOK; m++) o += S[n][m] * vs[m][d];
        g_attno[(size_t)(win * NTOK + n) * Cdim + head * HDIM + d] = o;
    }
}

// ------------------------------ launcher -----------------------------------
extern "C" void kernel_launch(void* const* d_in, const int* in_sizes, int n_in,
                              void* d_out, int out_size) {
    const float* x      = (const float*)d_in[0];
    const float* qkv_w  = (const float*)d_in[1];
    const float* qkv_b  = (const float*)d_in[2];
    const float* proj_w = (const float*)d_in[3];
    const float* proj_b = (const float*)d_in[4];
    const float* rpb    = (const float*)d_in[5];
    const float* ln1_g  = (const float*)d_in[6];
    const float* ln1_b  = (const float*)d_in[7];
    const float* ln2_g  = (const float*)d_in[8];
    const float* ln2_b  = (const float*)d_in[9];
    const float* w1     = (const float*)d_in[10];
    const float* b1     = (const float*)d_in[11];
    const float* w2     = (const float*)d_in[12];
    const float* b2     = (const float*)d_in[13];
    float* out = (float*)d_out;

    float *p_win, *p_qkv, *p_attno, *p_h, *p_ln2, *p_hid;
    cudaGetSymbolAddress((void**)&p_win,   g_win);
    cudaGetSymbolAddress((void**)&p_qkv,   g_qkv);
    cudaGetSymbolAddress((void**)&p_attno, g_attno);
    cudaGetSymbolAddress((void**)&p_h,     g_h);
    cudaGetSymbolAddress((void**)&p_ln2,   g_ln2);
    cudaGetSymbolAddress((void**)&p_hid,   g_hid);

    // 1. LN1 + shifted-window partition
    ln_kernel<<<MROWS, Cdim>>>(x, ln1_g, ln1_b, p_win, 1);

    // 2. QKV GEMM: (100352,192) @ (192,576)
    sgemm_kernel<0><<<dim3(3 * Cdim / 64, MROWS / 64), 256>>>(
        p_win, qkv_w, qkv_b, p_qkv, MROWS, 3 * Cdim, Cdim, nullptr);

    // 3. windowed attention (rpb + shift mask + softmax + PV)
    attn_kernel<<<NWIN * NHEADS, 256>>>(rpb);

    // 4. proj GEMM + window-reverse/roll + residual(x) -> g_h
    sgemm_kernel<2><<<dim3(Cdim / 64, MROWS / 64), 256>>>(
        p_attno, proj_w, proj_b, p_h, MROWS, Cdim, Cdim, x);

    // 5. LN2
    ln_kernel<<<MROWS, Cdim>>>(p_h, ln2_g, ln2_b, p_ln2, 0);

    // 6. MLP1 + GELU: (100352,192) @ (192,768)
    sgemm_kernel<1><<<dim3(HID / 64, MROWS / 64), 256>>>(
        p_ln2, w1, b1, p_hid, MROWS, HID, Cdim, nullptr);

    // 7. MLP2 + residual(g_h) -> out
    sgemm_kernel<3><<<dim3(Cdim / 64, MROWS / 64), 256>>>(
        p_hid, w2, b2, out, MROWS, Cdim, HID, p_h);
}

// round 2
// speedup vs baseline: 1.1654x; 1.1654x over previous
#include <cuda_runtime.h>
#include <cstdint>

// ---------------------------------------------------------------------------
// SwinBlock: B=32, H=W=56, C=192, heads=6, head_dim=32, WS=7, SS=3, N=49
// ---------------------------------------------------------------------------

#define Bsz     32
#define HW      56
#define Cdim    192
#define NHEADS  6
#define HDIM    32
#define WSZ     7
#define SSH     3
#define NTOK    49
#define NWIN    2048
#define MROWS   100352
#define HID     768
#define SCALE   0.17677669529663687f

// -------------------------- scratch (device globals) -----------------------
__device__ __align__(16) float g_win  [(size_t)MROWS * Cdim];
__device__ __align__(16) float g_qkv  [(size_t)MROWS * 3 * Cdim];
__device__ __align__(16) float g_attno[(size_t)MROWS * Cdim];
__device__ __align__(16) float g_h    [(size_t)MROWS * Cdim];
__device__ __align__(16) float g_ln2  [(size_t)MROWS * Cdim];
__device__ __align__(16) float g_hid  [(size_t)MROWS * HID];

__device__ __forceinline__ int permrow(int rw) {
    int win = rw / NTOK, n = rw - win * NTOK;
    int b   = win >> 6, wi = win & 63;
    int wh  = wi >> 3,  ww = wi & 7;
    int i   = n / WSZ,  j  = n - i * WSZ;
    int hs  = wh * WSZ + i + SSH; if (hs >= HW) hs -= HW;
    int ws  = ww * WSZ + j + SSH; if (ws >= HW) ws -= HW;
    return b * (HW * HW) + hs * HW + ws;
}

// ------------------------------ LayerNorm ----------------------------------
__global__ void ln_kernel(const float* __restrict__ in,
                          const float* __restrict__ gamma,
                          const float* __restrict__ beta,
                          float* __restrict__ out, int remap) {
    int rw = blockIdx.x;
    int c  = threadIdx.x;
    int src = remap ? permrow(rw) : rw;
    float v = in[(size_t)src * Cdim + c];

    __shared__ float red[6];
    float s = v;
    #pragma unroll
    for (int o = 16; o; o >>= 1) s += __shfl_xor_sync(0xffffffffu, s, o);
    if ((c & 31) == 0) red[c >> 5] = s;
    __syncthreads();
    float mu = 0.f;
    #pragma unroll
    for (int w = 0; w < 6; w++) mu += red[w];
    mu *= (1.0f / Cdim);
    __syncthreads();

    float d = v - mu;
    float sq = d * d;
    #pragma unroll
    for (int o = 16; o; o >>= 1) sq += __shfl_xor_sync(0xffffffffu, sq, o);
    if ((c & 31) == 0) red[c >> 5] = sq;
    __syncthreads();
    float var = 0.f;
    #pragma unroll
    for (int w = 0; w < 6; w++) var += red[w];
    var *= (1.0f / Cdim);

    out[(size_t)rw * Cdim + c] = d * rsqrtf(var + 1e-5f) * gamma[c] + beta[c];
}

// ------------------------------- SGEMM -------------------------------------
// 128x64 tile, 128 threads, 8x8 per-thread, double-buffered, cp.async for B.
// EPI: 0 plain, 1 GELU, 2 permrow+resid, 3 +resid
template<int EPI>
__global__ __launch_bounds__(128, 4)
void sgemm_kernel(const float* __restrict__ A, const float* __restrict__ Bm,
                  const float* __restrict__ bias, float* __restrict__ C,
                  int M, int N, int K, const float* __restrict__ resid) {
    __shared__ float As[2][16][132];   // k-major, padded (2-way STS conflict max)
    __shared__ float Bs[2][16][64];

    int tid = threadIdx.x;
    int tx = tid & 7, ty = tid >> 3;           // 8 x 16
    int mBase = blockIdx.y * 128, nBase = blockIdx.x * 64;

    int arow = tid >> 2;                       // +32*i
    int akc  = (tid & 3) * 4;
    int brow = tid >> 4;                       // +8*i
    int bcol = (tid & 15) * 4;

    const float* Ap = A + (size_t)(mBase + arow) * K + akc;
    const float* Bp = Bm + (size_t)brow * N + nBase + bcol;

    float4 areg[4];
    float acc[8][8] = {};

    // ---- prologue: stage 0 ----
    #pragma unroll
    for (int i = 0; i < 4; i++) areg[i] = *(const float4*)(Ap + (size_t)(32 * i) * K);
    #pragma unroll
    for (int i = 0; i < 2; i++) {
        uint32_t dst = (uint32_t)__cvta_generic_to_shared(&Bs[0][brow + 8 * i][bcol]);
        const float* src = Bp + (size_t)(8 * i) * N;
        asm volatile("cp.async.ca.shared.global [%0], [%1], 16;" :: "r"(dst), "l"(src));
    }
    asm volatile("cp.async.commit_group;");
    #pragma unroll
    for (int i = 0; i < 4; i++) {
        As[0][akc + 0][arow + 32 * i] = areg[i].x;
        As[0][akc + 1][arow + 32 * i] = areg[i].y;
        As[0][akc + 2][arow + 32 * i] = areg[i].z;
        As[0][akc + 3][arow + 32 * i] = areg[i].w;
    }
    asm volatile("cp.async.wait_group 0;");
    __syncthreads();

    int cur = 0;
    for (int k0 = 0; k0 < K; k0 += 16) {
        int nxt = cur ^ 1;
        bool has = (k0 + 16) < K;
        if (has) {
            const float* Ap2 = Ap + k0 + 16;
            #pragma unroll
            for (int i = 0; i < 4; i++) areg[i] = *(const float4*)(Ap2 + (size_t)(32 * i) * K);
            #pragma unroll
            for (int i = 0; i < 2; i++) {
                uint32_t dst = (uint32_t)__cvta_generic_to_shared(&Bs[nxt][brow + 8 * i][bcol]);
                const float* src = Bp + (size_t)(k0 + 16 + 8 * i) * N;
                asm volatile("cp.async.ca.shared.global [%0], [%1], 16;" :: "r"(dst), "l"(src));
            }
            asm volatile("cp.async.commit_group;");
        }

        #pragma unroll
        for (int kk = 0; kk < 16; kk++) {
            float4 a0 = *(const float4*)&As[cur][kk][ty * 8];
            float4 a1 = *(const float4*)&As[cur][kk][ty * 8 + 4];
            float4 b0 = *(const float4*)&Bs[cur][kk][tx * 8];
            float4 b1 = *(const float4*)&Bs[cur][kk][tx * 8 + 4];
            float a[8] = {a0.x, a0.y, a0.z, a0.w, a1.x, a1.y, a1.z, a1.w};
            float b[8] = {b0.x, b0.y, b0.z, b0.w, b1.x, b1.y, b1.z, b1.w};
            #pragma unroll
            for (int i = 0; i < 8; i++)
                #pragma unroll
                for (int j = 0; j < 8; j++)
                    acc[i][j] += a[i] * b[j];
        }

        if (has) {
            #pragma unroll
            for (int i = 0; i < 4; i++) {
                As[nxt][akc + 0][arow + 32 * i] = areg[i].x;
                As[nxt][akc + 1][arow + 32 * i] = areg[i].y;
                As[nxt][akc + 2][arow + 32 * i] = areg[i].z;
                As[nxt][akc + 3][arow + 32 * i] = areg[i].w;
            }
            asm volatile("cp.async.wait_group 0;");
        }
        __syncthreads();
        cur = nxt;
    }

    // ---- epilogue ----
    float4 bia0 = *(const float4*)&bias[nBase + tx * 8];
    float4 bia1 = *(const float4*)&bias[nBase + tx * 8 + 4];
    float bv[8] = {bia0.x, bia0.y, bia0.z, bia0.w, bia1.x, bia1.y, bia1.z, bia1.w};

    #pragma unroll
    for (int i = 0; i < 8; i++) {
        int row = mBase + ty * 8 + i;
        int prow = row;
        if (EPI == 2) prow = permrow(row);
        float v[8];
        #pragma unroll
        for (int j = 0; j < 8; j++) {
            v[j] = acc[i][j] + bv[j];
            if (EPI == 1)
                v[j] = 0.5f * v[j] * (1.0f + erff(v[j] * 0.70710678118654752f));
        }
        if (EPI == 2) {
            const float4* rp = (const float4*)&resid[(size_t)prow * Cdim + nBase + tx * 8];
            float4 r0 = rp[0], r1 = rp[1];
            v[0] += r0.x; v[1] += r0.y; v[2] += r0.z; v[3] += r0.w;
            v[4] += r1.x; v[5] += r1.y; v[6] += r1.z; v[7] += r1.w;
        } else if (EPI == 3) {
            const float4* rp = (const float4*)&resid[(size_t)row * N + nBase + tx * 8];
            float4 r0 = rp[0], r1 = rp[1];
            v[0] += r0.x; v[1] += r0.y; v[2] += r0.z; v[3] += r0.w;
            v[4] += r1.x; v[5] += r1.y; v[6] += r1.z; v[7] += r1.w;
        }
        float4* cp = (float4*)&C[(size_t)prow * N + nBase + tx * 8];
        cp[0] = make_float4(v[0], v[1], v[2], v[3]);
        cp[1] = make_float4(v[4], v[5], v[6], v[7]);
    }
}

// ----------------------------- Attention -----------------------------------
__global__ __launch_bounds__(256)
void attn_kernel(const float* __restrict__ rpb_table) {
    __shared__ float qs[NTOK][HDIM];
    __shared__ float ks[NTOK][HDIM];
    __shared__ float vs[NTOK][HDIM];
    __shared__ float S[NTOK][NTOK];

    int win  = blockIdx.x / NHEADS;
    int head = blockIdx.x - win * NHEADS;
    int tid  = threadIdx.x;

    int wi = win & 63;
    int wh = wi >> 3, ww = wi & 7;

    const float* base = g_qkv + (size_t)win * NTOK * (3 * Cdim) + head * HDIM;

    // load q/k/v tiles (float4)
    for (int idx = tid; idx < NTOK * 8; idx += 256) {
        int n = idx >> 3, dg = idx & 7;
        const float4* r = (const float4*)(base + (size_t)n * (3 * Cdim));
        float4 q = r[dg];
        q.x *= SCALE; q.y *= SCALE; q.z *= SCALE; q.w *= SCALE;
        ((float4*)qs[n])[dg] = q;
        ((float4*)ks[n])[dg] = r[(Cdim / 4) + dg];
        ((float4*)vs[n])[dg] = r[(2 * Cdim / 4) + dg];
    }
    __syncthreads();

    // S[i][j] = q_i . k_j + rpb + mask  (float4 over d)
    for (int e = tid; e < NTOK * NTOK; e += 256) {
        int i = e / NTOK, j = e - i * NTOK;
        const float4* qp = (const float4*)qs[i];
        const float4* kp = (const float4*)ks[j];
        float dot = 0.f;
        #pragma unroll
        for (int d = 0; d < 8; d++) {
            float4 qv = qp[d], kv = kp[d];
            dot += qv.x * kv.x + qv.y * kv.y + qv.z * kv.z + qv.w * kv.w;
        }

        int ri = i / WSZ, ci = i - ri * WSZ;
        int rj = j / WSZ, cj = j - rj * WSZ;
        int rpi = (ri - rj + 6) * 13 + (ci - cj + 6);
        dot += rpb_table[rpi * NHEADS + head];

        int hi = wh * WSZ + ri, wiC = ww * WSZ + ci;
        int hj = wh * WSZ + rj, wjC = ww * WSZ + cj;
        int gi = (hi < 49 ? 0 : (hi < 53 ? 1 : 2)) * 3 + (wiC < 49 ? 0 : (wiC < 53 ? 1 : 2));
        int gj = (hj < 49 ? 0 : (hj < 53 ? 1 : 2)) * 3 + (wjC < 49 ? 0 : (wjC < 53 ? 1 : 2));
        if (gi != gj) dot -= 100.0f;

        S[i][j] = dot;
    }
    __syncthreads();

    // softmax (warp per row)
    int warp = tid >> 5, lane = tid & 31;
    for (int r = warp; r < NTOK; r += 8) {
        float v0 = (lane < NTOK) ? S[r][lane] : -1e30f;
        float v1 = (lane + 32 < NTOK) ? S[r][lane + 32] : -1e30f;
        float m = fmaxf(v0, v1);
        #pragma unroll
        for (int o = 16; o; o >>= 1) m = fmaxf(m, __shfl_xor_sync(0xffffffffu, m, o));
        float e0 = (lane < NTOK) ? __expf(v0 - m) : 0.f;
        float e1 = (lane + 32 < NTOK) ? __expf(v1 - m) : 0.f;
        float s = e0 + e1;
        #pragma unroll
        for (int o = 16; o; o >>= 1) s += __shfl_xor_sync(0xffffffffu, s, o);
        float inv = __fdividef(1.0f, s);
        if (lane < NTOK)      S[r][lane]      = e0 * inv;
        if (lane + 32 < NTOK) S[r][lane + 32] = e1 * inv;
    }
    __syncthreads();

    // O = P @ V  (float4 over d)
    for (int e = tid; e < NTOK * 8; e += 256) {
        int n = e >> 3, dg = e & 7;
        float4 acc = make_float4(0.f, 0.f, 0.f, 0.f);
        #pragma unroll 7
        for (int m = 0; m < NTOK; m++) {
            float s = S[n][m];
            float4 v = ((const float4*)vs[m])[dg];
            acc.x += s * v.x; acc.y += s * v.y; acc.z += s * v.z; acc.w += s * v.w;
        }
        *(float4*)&g_attno[(size_t)(win * NTOK + n) * Cdim + head * HDIM + dg * 4] = acc;
    }
}

// ------------------------------ launcher -----------------------------------
extern "C" void kernel_launch(void* const* d_in, const int* in_sizes, int n_in,
                              void* d_out, int out_size) {
    const float* x      = (const float*)d_in[0];
    const float* qkv_w  = (const float*)d_in[1];
    const float* qkv_b  = (const float*)d_in[2];
    const float* proj_w = (const float*)d_in[3];
    const float* proj_b = (const float*)d_in[4];
    const float* rpb    = (const float*)d_in[5];
    const float* ln1_g  = (const float*)d_in[6];
    const float* ln1_b  = (const float*)d_in[7];
    const float* ln2_g  = (const float*)d_in[8];
    const float* ln2_b  = (const float*)d_in[9];
    const float* w1     = (const float*)d_in[10];
    const float* b1     = (const float*)d_in[11];
    const float* w2     = (const float*)d_in[12];
    const float* b2     = (const float*)d_in[13];
    float* out = (float*)d_out;

    float *p_win, *p_qkv, *p_attno, *p_h, *p_ln2, *p_hid;
    cudaGetSymbolAddress((void**)&p_win,   g_win);
    cudaGetSymbolAddress((void**)&p_qkv,   g_qkv);
    cudaGetSymbolAddress((void**)&p_attno, g_attno);
    cudaGetSymbolAddress((void**)&p_h,     g_h);
    cudaGetSymbolAddress((void**)&p_ln2,   g_ln2);
    cudaGetSymbolAddress((void**)&p_hid,   g_hid);

    ln_kernel<<<MROWS, Cdim>>>(x, ln1_g, ln1_b, p_win, 1);

    sgemm_kernel<0><<<dim3(3 * Cdim / 64, MROWS / 128), 128>>>(
        p_win, qkv_w, qkv_b, p_qkv, MROWS, 3 * Cdim, Cdim, nullptr);

    attn_kernel<<<NWIN * NHEADS, 256>>>(rpb);

    sgemm_kernel<2><<<dim3(Cdim / 64, MROWS / 128), 128>>>(
        p_attno, proj_w, proj_b, p_h, MROWS, Cdim, Cdim, x);

    ln_kernel<<<MROWS, Cdim>>>(p_h, ln2_g, ln2_b, p_ln2, 0);

    sgemm_kernel<1><<<dim3(HID / 64, MROWS / 128), 128>>>(
        p_ln2, w1, b1, p_hid, MROWS, HID, Cdim, nullptr);

    sgemm_kernel<3><<<dim3(Cdim / 64, MROWS / 128), 128>>>(
        p_hid, w2, b2, out, MROWS, Cdim, HID, p_h);
}

// round 4
// speedup vs baseline: 1.9179x; 1.6458x over previous
#include <cuda_runtime.h>
#include <cstdint>

// ---------------------------------------------------------------------------
// SwinBlock: B=32, H=W=56, C=192, heads=6, head_dim=32, WS=7, SS=3, N=49
// tf32 mma.sync GEMMs (sm_103 plain target - no tcgen05) + fused epilogues.
// ---------------------------------------------------------------------------

#define HW      56
#define Cdim    192
#define NHEADS  6
#define HDIM    32
#define WSZ     7
#define SSH     3
#define NTOK    49
#define NWIN    2048
#define MROWS   100352
#define HID     768
#define SCALE   0.17677669529663687f

// -------------------------- scratch (device globals) -----------------------
__device__ __align__(16) float g_win  [(size_t)MROWS * Cdim];
__device__ __align__(16) float g_qkv  [(size_t)MROWS * 3 * Cdim];
__device__ __align__(16) float g_attno[(size_t)MROWS * Cdim];
__device__ __align__(16) float g_h    [(size_t)MROWS * Cdim];
__device__ __align__(16) float g_ln2  [(size_t)MROWS * Cdim];
__device__ __align__(16) float g_hid  [(size_t)MROWS * HID];
__device__ __align__(16) float g_qkvwT[576 * 192];
__device__ __align__(16) float g_projwT[192 * 192];
__device__ __align__(16) float g_w1T  [HID * 192];
__device__ __align__(16) float g_w2T  [192 * HID];

// ------------------------------ helpers ------------------------------------
__device__ __forceinline__ float rn_tf32(float x) {
    float y;
    asm("cvt.rna.tf32.f32 %0, %1;" : "=f"(y) : "f"(x));
    return y;
}
__device__ __forceinline__ void cpasync16(void* dst, const void* src) {
    uint32_t d = (uint32_t)__cvta_generic_to_shared(dst);
    asm volatile("cp.async.cg.shared.global [%0], [%1], 16;" :: "r"(d), "l"(src));
}
#define CP_COMMIT() asm volatile("cp.async.commit_group;" ::: "memory")

__device__ __forceinline__ void mma_tf32(float* d, const float* a, const float* b) {
    asm volatile(
        "mma.sync.aligned.m16n8k8.row.col.f32.tf32.tf32.f32 "
        "{%0,%1,%2,%3}, {%4,%5,%6,%7}, {%8,%9}, {%0,%1,%2,%3};"
        : "+f"(d[0]), "+f"(d[1]), "+f"(d[2]), "+f"(d[3])
        : "r"(__float_as_uint(a[0])), "r"(__float_as_uint(a[1])),
          "r"(__float_as_uint(a[2])), "r"(__float_as_uint(a[3])),
          "r"(__float_as_uint(b[0])), "r"(__float_as_uint(b[1])));
}

__device__ __forceinline__ int permrow(int rw) {
    int win = rw / NTOK, n = rw - win * NTOK;
    int b   = win >> 6, wi = win & 63;
    int wh  = wi >> 3,  ww = wi & 7;
    int i   = n / WSZ,  j  = n - i * WSZ;
    int hs  = wh * WSZ + i + SSH; if (hs >= HW) hs -= HW;
    int ws  = ww * WSZ + j + SSH; if (ws >= HW) ws -= HW;
    return b * (HW * HW) + hs * HW + ws;
}

// ------------------------- weight transpose (+tf32 round) ------------------
__global__ void transpose_kernel(const float* __restrict__ in, float* __restrict__ out,
                                 int R, int C) {
    __shared__ float t[32][33];
    int bx = blockIdx.x * 32, by = blockIdx.y * 32;
    int x = threadIdx.x, y0 = threadIdx.y;
    #pragma unroll
    for (int j = 0; j < 32; j += 8)
        t[y0 + j][x] = in[(size_t)(by + y0 + j) * C + bx + x];
    __syncthreads();
    #pragma unroll
    for (int j = 0; j < 32; j += 8)
        out[(size_t)(bx + y0 + j) * R + by + x] = rn_tf32(t[x][y0 + j]);
}

// ------------------------------ LayerNorm (warp/row) -----------------------
__global__ __launch_bounds__(256)
void ln_kernel(const float* __restrict__ in, const float* __restrict__ gamma,
               const float* __restrict__ beta, float* __restrict__ out, int remap) {
    int wid = threadIdx.x >> 5, lane = threadIdx.x & 31;
    int row = blockIdx.x * 8 + wid;
    int src = remap ? permrow(row) : row;
    const float* p = in + (size_t)src * Cdim;

    float v[6];
    #pragma unroll
    for (int j = 0; j < 6; j++) v[j] = p[lane + 32 * j];
    float s = v[0] + v[1] + v[2] + v[3] + v[4] + v[5];
    #pragma unroll
    for (int o = 16; o; o >>= 1) s += __shfl_xor_sync(0xffffffffu, s, o);
    float mu = s * (1.0f / Cdim);
    float sq = 0.f;
    #pragma unroll
    for (int j = 0; j < 6; j++) { v[j] -= mu; sq += v[j] * v[j]; }
    #pragma unroll
    for (int o = 16; o; o >>= 1) sq += __shfl_xor_sync(0xffffffffu, sq, o);
    float inv = rsqrtf(sq * (1.0f / Cdim) + 1e-5f);
    float* q = out + (size_t)row * Cdim;
    #pragma unroll
    for (int j = 0; j < 6; j++) {
        int c = lane + 32 * j;
        q[c] = rn_tf32(v[j] * inv * gamma[c] + beta[c]);
    }
}

// --------------------------- tf32 mma.sync GEMM ----------------------------
// C[M,N] = A[M,K] @ BT[N,K]^T. CTA 128x96, 8 warps (2x4), warp 64x24.
// EPI: 0 plain, 1 GELU(+tf32 round), 2 permrow + resid(x), 3 + resid
template<int EPI>
__global__ __launch_bounds__(256, 2)
void tc_gemm(const float* __restrict__ A, const float* __restrict__ BT,
             const float* __restrict__ bias, float* __restrict__ C,
             int N, int K, const float* __restrict__ resid) {
    __shared__ float As[2][128][20];
    __shared__ float Bs[2][96][20];

    int tid  = threadIdx.x;
    int wid  = tid >> 5, lane = tid & 31;
    int g    = lane >> 2, tig = lane & 3;
    int wm   = wid & 1, wn = wid >> 1;         // 2 x 4 warp grid
    int mBase = blockIdx.x * 128;
    int nBase = blockIdx.y * 96;
    int nk = K >> 4;

    float acc[4][3][4];
    #pragma unroll
    for (int mt = 0; mt < 4; mt++)
        #pragma unroll
        for (int nt = 0; nt < 3; nt++)
            #pragma unroll
            for (int e = 0; e < 4; e++) acc[mt][nt][e] = 0.f;

    // chunk loader (k16): A 512 x 16B, B 384 x 16B
    auto load_chunk = [&](int buf, int k0) {
        #pragma unroll
        for (int i = 0; i < 2; i++) {
            int idx = tid + i * 256;
            int r = idx >> 2, ch = idx & 3;
            cpasync16(&As[buf][r][ch * 4],
                      A + (size_t)(mBase + r) * K + k0 + ch * 4);
        }
        {
            int r = tid >> 2, ch = tid & 3;
            cpasync16(&Bs[buf][r][ch * 4],
                      BT + (size_t)(nBase + r) * K + k0 + ch * 4);
        }
        if (tid < 128) {
            int idx = tid + 256;
            int r = idx >> 2, ch = idx & 3;
            cpasync16(&Bs[buf][r][ch * 4],
                      BT + (size_t)(nBase + r) * K + k0 + ch * 4);
        }
        CP_COMMIT();
    };

    load_chunk(0, 0);

    for (int kt = 0; kt < nk; kt++) {
        int buf = kt & 1;
        if (kt + 1 < nk) {
            load_chunk(buf ^ 1, (kt + 1) << 4);
            asm volatile("cp.async.wait_group 1;" ::: "memory");
        } else {
            asm volatile("cp.async.wait_group 0;" ::: "memory");
        }
        __syncthreads();

        #pragma unroll
        for (int s = 0; s < 2; s++) {
            int kf = s * 8 + tig;
            float a[4][4], b[3][2];
            #pragma unroll
            for (int mt = 0; mt < 4; mt++) {
                int r = wm * 64 + mt * 16 + g;
                a[mt][0] = As[buf][r][kf];
                a[mt][1] = As[buf][r + 8][kf];
                a[mt][2] = As[buf][r][kf + 4];
                a[mt][3] = As[buf][r + 8][kf + 4];
            }
            #pragma unroll
            for (int nt = 0; nt < 3; nt++) {
                int n = wn * 24 + nt * 8 + g;
                b[nt][0] = Bs[buf][n][kf];
                b[nt][1] = Bs[buf][n][kf + 4];
            }
            #pragma unroll
            for (int mt = 0; mt < 4; mt++)
                #pragma unroll
                for (int nt = 0; nt < 3; nt++)
                    mma_tf32(acc[mt][nt], a[mt], b[nt]);
        }
        __syncthreads();
    }

    // ---------------- epilogue from accumulators ----------------
    #pragma unroll
    for (int mt = 0; mt < 4; mt++) {
        int r0 = mBase + wm * 64 + mt * 16 + g;
        int r1 = r0 + 8;
        int p0 = r0, p1 = r1;
        if (EPI == 2) { p0 = permrow(r0); p1 = permrow(r1); }
        #pragma unroll
        for (int nt = 0; nt < 3; nt++) {
            int c = nBase + wn * 24 + nt * 8 + 2 * tig;
            float2 bv = *(const float2*)(bias + c);
            float v0 = acc[mt][nt][0] + bv.x;
            float v1 = acc[mt][nt][1] + bv.y;
            float v2 = acc[mt][nt][2] + bv.x;
            float v3 = acc[mt][nt][3] + bv.y;
            if (EPI == 1) {
                v0 = rn_tf32(0.5f * v0 * (1.0f + erff(v0 * 0.70710678118654752f)));
                v1 = rn_tf32(0.5f * v1 * (1.0f + erff(v1 * 0.70710678118654752f)));
                v2 = rn_tf32(0.5f * v2 * (1.0f + erff(v2 * 0.70710678118654752f)));
                v3 = rn_tf32(0.5f * v3 * (1.0f + erff(v3 * 0.70710678118654752f)));
            } else if (EPI == 2) {
                float2 ra = *(const float2*)(resid + (size_t)p0 * Cdim + c);
                float2 rb = *(const float2*)(resid + (size_t)p1 * Cdim + c);
                v0 += ra.x; v1 += ra.y; v2 += rb.x; v3 += rb.y;
            } else if (EPI == 3) {
                float2 ra = *(const float2*)(resid + (size_t)r0 * Cdim + c);
                float2 rb = *(const float2*)(resid + (size_t)r1 * Cdim + c);
                v0 += ra.x; v1 += ra.y; v2 += rb.x; v3 += rb.y;
            }
            *(float2*)(C + (size_t)p0 * N + c) = make_float2(v0, v1);
            *(float2*)(C + (size_t)p1 * N + c) = make_float2(v2, v3);
        }
    }
}

// ----------------------------- Attention -----------------------------------
__global__ __launch_bounds__(256)
void attn_kernel(const float* __restrict__ rpb_table) {
    __shared__ float qs[NTOK][HDIM];
    __shared__ float ks[NTOK][HDIM];
    __shared__ float vs[NTOK][HDIM];
    __shared__ float S[NTOK][NTOK];

    int win  = blockIdx.x / NHEADS;
    int head = blockIdx.x - win * NHEADS;
    int tid  = threadIdx.x;
    int wi = win & 63;
    int wh = wi >> 3, ww = wi & 7;

    const float* base = g_qkv + (size_t)win * NTOK * (3 * Cdim) + head * HDIM;

    for (int idx = tid; idx < NTOK * 8; idx += 256) {
        int n = idx >> 3, dg = idx & 7;
        const float4* r = (const float4*)(base + (size_t)n * (3 * Cdim));
        float4 q = r[dg];
        q.x *= SCALE; q.y *= SCALE; q.z *= SCALE; q.w *= SCALE;
        ((float4*)qs[n])[dg] = q;
        ((float4*)ks[n])[dg] = r[(Cdim / 4) + dg];
        ((float4*)vs[n])[dg] = r[(2 * Cdim / 4) + dg];
    }
    __syncthreads();

    for (int e = tid; e < NTOK * NTOK; e += 256) {
        int i = e / NTOK, j = e - i * NTOK;
        const float4* qp = (const float4*)qs[i];
        const float4* kp = (const float4*)ks[j];
        float dot = 0.f;
        #pragma unroll
        for (int d = 0; d < 8; d++) {
            float4 qv = qp[d], kv = kp[d];
            dot += qv.x * kv.x + qv.y * kv.y + qv.z * kv.z + qv.w * kv.w;
        }
        int ri = i / WSZ, ci = i - ri * WSZ;
        int rj = j / WSZ, cj = j - rj * WSZ;
        dot += rpb_table[((ri - rj + 6) * 13 + (ci - cj + 6)) * NHEADS + head];
        int hi = wh * WSZ + ri, wiC = ww * WSZ + ci;
        int hj = wh * WSZ + rj, wjC = ww * WSZ + cj;
        int gi = (hi < 49 ? 0 : (hi < 53 ? 1 : 2)) * 3 + (wiC < 49 ? 0 : (wiC < 53 ? 1 : 2));
        int gj = (hj < 49 ? 0 : (hj < 53 ? 1 : 2)) * 3 + (wjC < 49 ? 0 : (wjC < 53 ? 1 : 2));
        if (gi != gj) dot -= 100.0f;
        S[i][j] = dot;
    }
    __syncthreads();

    int warp = tid >> 5, lane = tid & 31;
    for (int r = warp; r < NTOK; r += 8) {
        float v0 = (lane < NTOK) ? S[r][lane] : -1e30f;
        float v1 = (lane + 32 < NTOK) ? S[r][lane + 32] : -1e30f;
        float m = fmaxf(v0, v1);
        #pragma unroll
        for (int o = 16; o; o >>= 1) m = fmaxf(m, __shfl_xor_sync(0xffffffffu, m, o));
        float e0 = (lane < NTOK) ? __expf(v0 - m) : 0.f;
        float e1 = (lane + 32 < NTOK) ? __expf(v1 - m) : 0.f;
        float s = e0 + e1;
        #pragma unroll
        for (int o = 16; o; o >>= 1) s += __shfl_xor_sync(0xffffffffu, s, o);
        float inv = __fdividef(1.0f, s);
        if (lane < NTOK)      S[r][lane]      = e0 * inv;
        if (lane + 32 < NTOK) S[r][lane + 32] = e1 * inv;
    }
    __syncthreads();

    for (int e = tid; e < NTOK * 8; e += 256) {
        int n = e >> 3, dg = e & 7;
        float4 acc = make_float4(0.f, 0.f, 0.f, 0.f);
        #pragma unroll 7
        for (int m = 0; m < NTOK; m++) {
            float s = S[n][m];
            float4 v = ((const float4*)vs[m])[dg];
            acc.x += s * v.x; acc.y += s * v.y; acc.z += s * v.z; acc.w += s * v.w;
        }
        acc.x = rn_tf32(acc.x); acc.y = rn_tf32(acc.y);
        acc.z = rn_tf32(acc.z); acc.w = rn_tf32(acc.w);
        *(float4*)&g_attno[(size_t)(win * NTOK + n) * Cdim + head * HDIM + dg * 4] = acc;
    }
}

// ------------------------------ launcher -----------------------------------
extern "C" void kernel_launch(void* const* d_in, const int* in_sizes, int n_in,
                              void* d_out, int out_size) {
    const float* x      = (const float*)d_in[0];
    const float* qkv_w  = (const float*)d_in[1];
    const float* qkv_b  = (const float*)d_in[2];
    const float* proj_w = (const float*)d_in[3];
    const float* proj_b = (const float*)d_in[4];
    const float* rpb    = (const float*)d_in[5];
    const float* ln1_g  = (const float*)d_in[6];
    const float* ln1_b  = (const float*)d_in[7];
    const float* ln2_g  = (const float*)d_in[8];
    const float* ln2_b  = (const float*)d_in[9];
    const float* w1     = (const float*)d_in[10];
    const float* b1     = (const float*)d_in[11];
    const float* w2     = (const float*)d_in[12];
    const float* b2     = (const float*)d_in[13];
    float* out = (float*)d_out;

    float *p_win, *p_qkv, *p_attno, *p_h, *p_ln2, *p_hid;
    float *p_qkvwT, *p_projwT, *p_w1T, *p_w2T;
    cudaGetSymbolAddress((void**)&p_win,    g_win);
    cudaGetSymbolAddress((void**)&p_qkv,    g_qkv);
    cudaGetSymbolAddress((void**)&p_attno,  g_attno);
    cudaGetSymbolAddress((void**)&p_h,      g_h);
    cudaGetSymbolAddress((void**)&p_ln2,    g_ln2);
    cudaGetSymbolAddress((void**)&p_hid,    g_hid);
    cudaGetSymbolAddress((void**)&p_qkvwT,  g_qkvwT);
    cudaGetSymbolAddress((void**)&p_projwT, g_projwT);
    cudaGetSymbolAddress((void**)&p_w1T,    g_w1T);
    cudaGetSymbolAddress((void**)&p_w2T,    g_w2T);

    dim3 tb(32, 8);
    transpose_kernel<<<dim3(576 / 32, 192 / 32), tb>>>(qkv_w,  p_qkvwT, 192, 576);
    transpose_kernel<<<dim3(192 / 32, 192 / 32), tb>>>(proj_w, p_projwT, 192, 192);
    transpose_kernel<<<dim3(HID / 32, 192 / 32), tb>>>(w1,     p_w1T,   192, HID);
    transpose_kernel<<<dim3(192 / 32, HID / 32), tb>>>(w2,     p_w2T,   HID, 192);

    // 1. LN1 + shifted-window partition (tf32-rounded out)
    ln_kernel<<<MROWS / 8, 256>>>(x, ln1_g, ln1_b, p_win, 1);

    // 2. QKV: (100352,192) @ (192,576)
    tc_gemm<0><<<dim3(MROWS / 128, 576 / 96), 256>>>(p_win, p_qkvwT, qkv_b, p_qkv, 576, 192, nullptr);

    // 3. windowed attention
    attn_kernel<<<NWIN * NHEADS, 256>>>(rpb);

    // 4. proj + window-reverse + residual(x)
    tc_gemm<2><<<dim3(MROWS / 128, 192 / 96), 256>>>(p_attno, p_projwT, proj_b, p_h, 192, 192, x);

    // 5. LN2
    ln_kernel<<<MROWS / 8, 256>>>(p_h, ln2_g, ln2_b, p_ln2, 0);

    // 6. MLP1 + GELU
    tc_gemm<1><<<dim3(MROWS / 128, HID / 96), 256>>>(p_ln2, p_w1T, b1, p_hid, HID, 192, nullptr);

    // 7. MLP2 + residual(h)
    tc_gemm<3><<<dim3(MROWS / 128, 192 / 96), 256>>>(p_hid, p_w2T, b2, out, 192, HID, p_h);
}